// round 16
// baseline (speedup 1.0000x reference)
#include <cuda_runtime.h>
#include <cuda_fp16.h>
#include <cstdint>

#define BB 8
#define TT 1024
#define EE 1024
#define HH 16
#define HD 64
#define FFD 4096
#define MM (BB*TT)          // 8192 rows
#define SCALE 0.125f        // HD^-0.5

// ---------------- scratch (device globals: allocation-free) ----------------
static __device__ float  g_y1[MM * EE];          // fp32 (LN1 out, FC2 residual)
static __device__ __half g_q[MM * 3 * EE];       // qkv fp16
static __device__ __half g_x[MM * EE];           // x fp16
static __device__ __half g_a[MM * EE];           // attn out fp16
static __device__ __half g_y1h[MM * EE];         // LN1 out fp16
static __device__ __half g_f[MM * FFD];          // FC1 out fp16
static __device__ __half g_wi[3*EE*EE];
static __device__ __half g_wo[EE*EE];
static __device__ __half g_w1[FFD*EE];
static __device__ __half g_w2[EE*FFD];
static __device__ int g_mask_mode;               // 0=u8, 1=i32, 2=f32

// ================= PTX helpers =================
__device__ __forceinline__ uint32_t smem_u32(const void* p) {
    uint32_t a;
    asm("{ .reg .u64 t; cvta.to.shared.u64 t, %1; cvt.u32.u64 %0, t; }"
        : "=r"(a) : "l"(p));
    return a;
}
__device__ __forceinline__ void ldsm4(uint32_t* r, uint32_t addr) {
    asm volatile("ldmatrix.sync.aligned.m8n8.x4.shared.b16 {%0,%1,%2,%3}, [%4];"
                 : "=r"(r[0]), "=r"(r[1]), "=r"(r[2]), "=r"(r[3]) : "r"(addr));
}
__device__ __forceinline__ void ldsm4t(uint32_t* r, uint32_t addr) {
    asm volatile("ldmatrix.sync.aligned.m8n8.x4.trans.shared.b16 {%0,%1,%2,%3}, [%4];"
                 : "=r"(r[0]), "=r"(r[1]), "=r"(r[2]), "=r"(r[3]) : "r"(addr));
}
__device__ __forceinline__ void mma16816(float* d, const uint32_t* a,
                                         uint32_t b0, uint32_t b1) {
    asm volatile(
        "mma.sync.aligned.m16n8k16.row.col.f32.f16.f16.f32 "
        "{%0,%1,%2,%3}, {%4,%5,%6,%7}, {%8,%9}, {%0,%1,%2,%3};"
        : "+f"(d[0]), "+f"(d[1]), "+f"(d[2]), "+f"(d[3])
        : "r"(a[0]), "r"(a[1]), "r"(a[2]), "r"(a[3]), "r"(b0), "r"(b1));
}
__device__ __forceinline__ void cpa16(uint32_t dst, const void* src) {
    asm volatile("cp.async.cg.shared.global [%0], [%1], 16;" :: "r"(dst), "l"(src));
}
__device__ __forceinline__ void cpa_commit() {
    asm volatile("cp.async.commit_group;" ::: "memory");
}
__device__ __forceinline__ void cpa_wait2() {
    asm volatile("cp.async.wait_group 2;" ::: "memory");
}
__device__ __forceinline__ void cpa_wait1() {
    asm volatile("cp.async.wait_group 1;" ::: "memory");
}
__device__ __forceinline__ void cpa_wait0() {
    asm volatile("cp.async.wait_group 0;" ::: "memory");
}
__device__ __forceinline__ float ex2f(float x) {
    float y;
    asm("ex2.approx.ftz.f32 %0, %1;" : "=f"(y) : "f"(x));
    return y;
}
__device__ __forceinline__ uint32_t packh2(float x, float y) {
    __half2 v = __float22half2_rn(make_float2(x, y));
    return *reinterpret_cast<uint32_t*>(&v);
}

// ---------------- mask dtype probe ----------------
__global__ void probe_mask(const unsigned char* __restrict__ p) {
    __shared__ int cnt[4];
    if (threadIdx.x < 4) cnt[threadIdx.x] = 0;
    __syncthreads();
    int local[4] = {0, 0, 0, 0};
    for (int i = threadIdx.x; i < 8192; i += blockDim.x)
        if (p[i]) local[i & 3]++;
    #pragma unroll
    for (int c = 0; c < 4; c++)
        if (local[c]) atomicAdd(&cnt[c], local[c]);
    __syncthreads();
    if (threadIdx.x == 0) {
        int c0 = cnt[0], c1 = cnt[1], c2 = cnt[2], c3 = cnt[3];
        int mode = 0;
        if (c0 > 0 && c1 == 0 && c2 == 0 && c3 == 0) mode = 1;
        else if (c0 == 0 && c1 == 0 && (c2 > 0 || c3 > 0)) mode = 2;
        g_mask_mode = mode;
    }
}

// ---------------- fp32 -> fp16 convert ----------------
__global__ __launch_bounds__(256) void convert_h(
    const float* __restrict__ in, __half* __restrict__ h, int n4)
{
    int i = blockIdx.x * blockDim.x + threadIdx.x;
    if (i >= n4) return;
    float4 v = ((const float4*)in)[i];
    __half2 h01 = __float22half2_rn(make_float2(v.x, v.y));
    __half2 h23 = __float22half2_rn(make_float2(v.z, v.w));
    ((__half2*)h)[2*i]   = h01;
    ((__half2*)h)[2*i+1] = h23;
}

// =================================================================
// fp16 HMMA GEMM: C = act(A @ W^T + bias (+R))
// A [M,K], W [N,K] fp16 K-major. 128x128 CTA tile, 4 warps (64x64),
// BK=64, 2-stage cp.async (64 KB smem -> 3 CTAs/SM), swizzled rows.
// =================================================================
#define STG_T 16384                // bytes/tensor/stage (128 rows * 128B)
#define STG_ALL 32768              // A | W
#define SMEMG (2 * STG_ALL)        // 64 KB

#define LOAD_STAGE(stg, ch) do { \
    const uint32_t _base = sb + (stg) * STG_ALL; \
    const int _ko = (ch) * 64; \
    _Pragma("unroll") \
    for (int i = 0; i < 16; i++) { \
        const int idx = i * 128 + tid; \
        const int t = idx >> 10; \
        const int c = idx & 1023; \
        const int row = c >> 3, g = c & 7; \
        const __half* _s = (t ? gW : gA) + (size_t)row * K + _ko + g * 8; \
        cpa16(_base + t * STG_T + row * 128 \
              + (((uint32_t)(g ^ (row & 7))) << 4), _s); \
    } \
} while (0)

template <int RELU, int RES, int OUTH>
__global__ __launch_bounds__(128, 3) void gemm_f16(
    const __half* __restrict__ A, const __half* __restrict__ W,
    const float* __restrict__ bias, const float* __restrict__ R,
    float* __restrict__ Cf, __half* __restrict__ Ch, int M, int N, int K)
{
    extern __shared__ char smem[];
    const uint32_t sb = smem_u32(smem);
    const int tid = threadIdx.x, lane = tid & 31, wid = tid >> 5;
    const int wm = wid & 1, wn = wid >> 1;
    const int m0 = blockIdx.y * 128, n0 = blockIdx.x * 128;

    const __half* gA = A + (size_t)m0 * K;
    const __half* gW = W + (size_t)n0 * K;

    const int r15 = lane & 15;
    const int hs  = lane >> 4;
    const uint32_t x7 = (uint32_t)(r15 & 7);

    float acc[4][8][4];
    #pragma unroll
    for (int a = 0; a < 4; a++)
        #pragma unroll
        for (int b = 0; b < 8; b++)
            #pragma unroll
            for (int c = 0; c < 4; c++) acc[a][b][c] = 0.f;

    const int nch = K >> 6;

    LOAD_STAGE(0, 0); cpa_commit();
    LOAD_STAGE(1, 1); cpa_commit();

    for (int ch = 0; ch < nch; ch++) {
        cpa_wait1();
        __syncthreads();

        const uint32_t st = sb + (ch & 1) * STG_ALL;
        #pragma unroll
        for (int kk = 0; kk < 4; kk++) {
            const uint32_t ksw = (((uint32_t)(2 * kk + hs)) ^ x7) << 4;
            uint32_t af[4][4], bf[4][4];
            #pragma unroll
            for (int mt = 0; mt < 4; mt++)
                ldsm4(af[mt], st + (uint32_t)(wm * 64 + mt * 16 + r15) * 128 + ksw);
            #pragma unroll
            for (int g = 0; g < 4; g++)
                ldsm4(bf[g], st + STG_T + (uint32_t)(wn * 64 + g * 16 + r15) * 128 + ksw);
            #pragma unroll
            for (int mt = 0; mt < 4; mt++) {
                #pragma unroll
                for (int g = 0; g < 4; g++) {
                    mma16816(acc[mt][2*g],   af[mt], bf[g][0], bf[g][2]);
                    mma16816(acc[mt][2*g+1], af[mt], bf[g][1], bf[g][3]);
                }
            }
        }

        if (ch + 2 < nch) {
            __syncthreads();
            LOAD_STAGE(ch & 1, ch + 2);
        }
        cpa_commit();
    }

    const int gr = lane >> 2;
    const int gc = (lane & 3) * 2;
    #pragma unroll
    for (int mt = 0; mt < 4; mt++) {
        #pragma unroll
        for (int half = 0; half < 2; half++) {
            const int m = m0 + wm * 64 + mt * 16 + gr + half * 8;
            #pragma unroll
            for (int nt = 0; nt < 8; nt++) {
                const int col = n0 + wn * 64 + nt * 8 + gc;
                float2 bv = *(const float2*)(bias + col);
                float ox = acc[mt][nt][2*half + 0] + bv.x;
                float oy = acc[mt][nt][2*half + 1] + bv.y;
                if (RES) {
                    float2 rv = *(const float2*)(R + (size_t)m * N + col);
                    ox += rv.x; oy += rv.y;
                }
                if (RELU) { ox = fmaxf(ox, 0.f); oy = fmaxf(oy, 0.f); }
                if (OUTH) {
                    *(__half2*)(Ch + (size_t)m * N + col) =
                        __float22half2_rn(make_float2(ox, oy));
                } else {
                    *(float2*)(Cf + (size_t)m * N + col) = make_float2(ox, oy);
                }
            }
        }
    }
}

// =================================================================
// fp16 tensor-core flash attention, 2-stage double-buffered K/V.
// 128 threads (4 warps), 64 queries/block, grid (16, 16, 8).
// smem: Q (8 KB) | KV stage0 (16 KB) | KV stage1 (16 KB) | bias[2][64]
// =================================================================
#define AQ 0
#define AKV 8192
#define KVSTG 16384
#define ABIAS (AKV + 2 * KVSTG)     // 40960
#define ATT_SMEM (ABIAS + 512)

#define LOADKV(st_, kt_) do { \
    const int _t0 = (kt_) * 64; \
    const uint32_t _kb = sb + AKV + (st_) * KVSTG; \
    _Pragma("unroll") \
    for (int i = 0; i < 8; i++) { \
        const int idx = i * 128 + tid; \
        const int t2 = idx >> 9; \
        const int c = idx & 511; \
        const int row = c >> 3, g = c & 7; \
        const __half* src = qkv \
            + (size_t)(b * TT + _t0 + row) * row3 \
            + EE + t2 * EE + h * HD + g * 8; \
        cpa16(_kb + t2 * 8192 + row * 128 \
              + (((uint32_t)(g ^ (row & 7))) << 4), src); \
    } \
    if (tid < 64) { \
        const int tk = _t0 + tid; \
        bool pm; \
        if (mode == 1)      pm = (((const int*)pad)[b * TT + tk] != 0); \
        else if (mode == 2) pm = (((const float*)pad)[b * TT + tk] != 0.f); \
        else                pm = (((const unsigned char*)pad)[b * TT + tk] != 0); \
        sbias[((st_) << 6) + tid] = pm ? -1e30f : 0.f; \
    } \
} while (0)

__global__ __launch_bounds__(128) void attn_mma(
    const __half* __restrict__ qkv,
    const void* __restrict__ pad,
    __half* __restrict__ outp)
{
    extern __shared__ char sm[];
    const uint32_t sb = smem_u32(sm);
    float* sbias = (float*)(sm + ABIAS);

    const int tid = threadIdx.x, lane = tid & 31, w = tid >> 5;
    const int qt = (int)gridDim.x - 1 - (int)blockIdx.x;   // LPT
    const int h = blockIdx.y, b = blockIdx.z;
    const int q0 = qt * 64;
    const int row3 = 3 * EE;
    const int mode = g_mask_mode;
    const int gr = lane >> 2;
    const int r15 = lane & 15;
    const int hs = lane >> 4;
    const uint32_t x7 = (uint32_t)(r15 & 7);

    // ---- stage Q, prefetch KV tiles 0 and 1 ----
    #pragma unroll
    for (int i = 0; i < 4; i++) {
        const int idx = i * 128 + tid;
        const int row = idx >> 3, g = idx & 7;
        const __half* src = qkv
            + (size_t)(b * TT + q0 + row) * row3 + h * HD + g * 8;
        cpa16(sb + row * 128 + (((uint32_t)(g ^ (row & 7))) << 4), src);
    }
    cpa_commit();
    LOADKV(0, 0); cpa_commit();
    if (qt >= 1) { LOADKV(1, 1); cpa_commit(); }
    if (qt >= 1) cpa_wait2(); else cpa_wait1();
    __syncthreads();

    uint32_t qf[4][4];
    #pragma unroll
    for (int kc = 0; kc < 4; kc++) {
        const uint32_t a = (uint32_t)(16 * w + r15) * 128
            + ((((uint32_t)(2 * kc + hs)) ^ x7) << 4);
        ldsm4(qf[kc], sb + AQ + a);
    }

    float m2[2] = {-1e30f, -1e30f};
    float lsum[2] = {0.f, 0.f};
    float o[8][4];
    #pragma unroll
    for (int nt = 0; nt < 8; nt++)
        #pragma unroll
        for (int i = 0; i < 4; i++) o[nt][i] = 0.f;

    const float cst = SCALE * 1.44269504f;

    for (int kt = 0; kt <= qt; kt++) {
        if (kt == qt) cpa_wait0(); else cpa_wait1();
        __syncthreads();

        const int st = kt & 1;
        const uint32_t kvb = sb + AKV + st * KVSTG;
        const float* sbst = sbias + (st << 6);
        const int t0 = kt * 64;

        // ---- S = Q K^T ----
        float s[8][4];
        #pragma unroll
        for (int nt = 0; nt < 8; nt++)
            #pragma unroll
            for (int i = 0; i < 4; i++) s[nt][i] = 0.f;

        #pragma unroll
        for (int kc = 0; kc < 4; kc++) {
            const uint32_t ksw = (((uint32_t)(2 * kc + hs)) ^ x7) << 4;
            uint32_t bh[4][4];
            #pragma unroll
            for (int g2 = 0; g2 < 4; g2++)
                ldsm4(bh[g2], kvb + (uint32_t)(16 * g2 + r15) * 128 + ksw);
            #pragma unroll
            for (int g2 = 0; g2 < 4; g2++) {
                mma16816(s[2*g2],   qf[kc], bh[g2][0], bh[g2][2]);
                mma16816(s[2*g2+1], qf[kc], bh[g2][1], bh[g2][3]);
            }
        }

        // ---- softmax (base-2, online) ----
        float ml0 = -1e30f, ml1 = -1e30f;
        const int diag = (kt == qt);
        #pragma unroll
        for (int nt = 0; nt < 8; nt++) {
            #pragma unroll
            for (int i = 0; i < 4; i++) {
                const int col = nt * 8 + 2 * (lane & 3) + (i & 1);
                float v = s[nt][i] * cst + sbst[col];
                if (diag) {
                    const int kg = t0 + col;
                    const int qg = q0 + 16 * w + gr + (i >> 1) * 8;
                    if (kg > qg) v = -1e30f;
                }
                s[nt][i] = v;
                if (i < 2) ml0 = fmaxf(ml0, v); else ml1 = fmaxf(ml1, v);
            }
        }
        ml0 = fmaxf(ml0, __shfl_xor_sync(0xffffffffu, ml0, 1));
        ml0 = fmaxf(ml0, __shfl_xor_sync(0xffffffffu, ml0, 2));
        ml1 = fmaxf(ml1, __shfl_xor_sync(0xffffffffu, ml1, 1));
        ml1 = fmaxf(ml1, __shfl_xor_sync(0xffffffffu, ml1, 2));
        const float mn0 = fmaxf(m2[0], ml0), mn1 = fmaxf(m2[1], ml1);
        const float al0 = ex2f(m2[0] - mn0), al1 = ex2f(m2[1] - mn1);
        m2[0] = mn0; m2[1] = mn1;

        float rs0 = 0.f, rs1 = 0.f;
        #pragma unroll
        for (int nt = 0; nt < 8; nt++) {
            #pragma unroll
            for (int i = 0; i < 4; i++) {
                const float p = ex2f(s[nt][i] - ((i < 2) ? mn0 : mn1));
                s[nt][i] = p;
                if (i < 2) rs0 += p; else rs1 += p;
            }
        }
        rs0 += __shfl_xor_sync(0xffffffffu, rs0, 1);
        rs0 += __shfl_xor_sync(0xffffffffu, rs0, 2);
        rs1 += __shfl_xor_sync(0xffffffffu, rs1, 1);
        rs1 += __shfl_xor_sync(0xffffffffu, rs1, 2);
        lsum[0] = lsum[0] * al0 + rs0;
        lsum[1] = lsum[1] * al1 + rs1;
        #pragma unroll
        for (int nt = 0; nt < 8; nt++) {
            o[nt][0] *= al0; o[nt][1] *= al0;
            o[nt][2] *= al1; o[nt][3] *= al1;
        }

        // ---- P fragments fp16 ----
        uint32_t pa[4][4];
        #pragma unroll
        for (int c = 0; c < 4; c++) {
            #pragma unroll
            for (int j = 0; j < 4; j++) {
                const int nt = 2 * c + (j >> 1);
                const int i0 = (j & 1) * 2;
                pa[c][j] = packh2(s[nt][i0], s[nt][i0 + 1]);
            }
        }

        // ---- O += P V ----
        #pragma unroll
        for (int c = 0; c < 4; c++) {
            uint32_t vh[4][4];
            #pragma unroll
            for (int g2 = 0; g2 < 4; g2++) {
                const uint32_t a = (uint32_t)(16 * c + r15) * 128
                    + ((((uint32_t)(2 * g2 + hs)) ^ x7) << 4);
                ldsm4t(vh[g2], kvb + 8192 + a);
            }
            #pragma unroll
            for (int g2 = 0; g2 < 4; g2++) {
                mma16816(o[2*g2],   pa[c], vh[g2][0], vh[g2][1]);
                mma16816(o[2*g2+1], pa[c], vh[g2][2], vh[g2][3]);
            }
        }

        if (kt + 2 <= qt) {
            __syncthreads();
            LOADKV(st, kt + 2);
            cpa_commit();
        }
    }

    // ---- epilogue ----
    const float inv0 = 1.f / lsum[0], inv1 = 1.f / lsum[1];
    #pragma unroll
    for (int r = 0; r < 2; r++) {
        const int row = q0 + 16 * w + gr + 8 * r;
        const float inv = r ? inv1 : inv0;
        const size_t base = (size_t)(b * TT + row) * EE + h * HD + 2 * (lane & 3);
        #pragma unroll
        for (int nt = 0; nt < 8; nt++) {
            *(__half2*)(outp + base + nt * 8) = __float22half2_rn(
                make_float2(o[nt][2*r] * inv, o[nt][2*r + 1] * inv));
        }
    }
}

// ---------------- LayerNorm in-place (+ optional fp16 emit) ----------------
template <int HL>
__global__ __launch_bounds__(256) void ln_kernel(
    float* __restrict__ X, const float* __restrict__ w,
    const float* __restrict__ bias, __half* __restrict__ Yh)
{
    __shared__ float red[8];
    const int row = blockIdx.x, tid = threadIdx.x;
    float4* xr = (float4*)(X + (size_t)row * EE);
    float4 v = xr[tid];

    float s = v.x + v.y + v.z + v.w;
    #pragma unroll
    for (int o = 16; o; o >>= 1) s += __shfl_xor_sync(0xffffffffu, s, o);
    if ((tid & 31) == 0) red[tid >> 5] = s;
    __syncthreads();
    float tot = red[0] + red[1] + red[2] + red[3] + red[4] + red[5] + red[6] + red[7];
    const float mean = tot * (1.f / EE);

    float dx = v.x - mean, dy = v.y - mean, dz = v.z - mean, dw = v.w - mean;
    float s2 = dx * dx + dy * dy + dz * dz + dw * dw;
    __syncthreads();
    #pragma unroll
    for (int o = 16; o; o >>= 1) s2 += __shfl_xor_sync(0xffffffffu, s2, o);
    if ((tid & 31) == 0) red[tid >> 5] = s2;
    __syncthreads();
    float tot2 = red[0] + red[1] + red[2] + red[3] + red[4] + red[5] + red[6] + red[7];
    const float var = tot2 * (1.f / EE);
    const float inv = rsqrtf(var + 1e-12f);

    float4 wv = ((const float4*)w)[tid];
    float4 bv = ((const float4*)bias)[tid];
    float4 r;
    r.x = dx * inv * wv.x + bv.x;
    r.y = dy * inv * wv.y + bv.y;
    r.z = dz * inv * wv.z + bv.z;
    r.w = dw * inv * wv.w + bv.w;
    xr[tid] = r;
    if (HL) {
        const size_t base = (size_t)row * EE + tid * 4;
        *(__half2*)(Yh + base)     = __float22half2_rn(make_float2(r.x, r.y));
        *(__half2*)(Yh + base + 2) = __float22half2_rn(make_float2(r.z, r.w));
    }
}

// ---------------- launch ----------------
extern "C" void kernel_launch(void* const* d_in, const int* in_sizes, int n_in,
                              void* d_out, int out_size)
{
    const float* x     = (const float*)d_in[0];
    const float* in_w  = (const float*)d_in[1];
    const float* in_b  = (const float*)d_in[2];
    const float* out_w = (const float*)d_in[3];
    const float* out_b = (const float*)d_in[4];
    const float* fc1_w = (const float*)d_in[5];
    const float* fc1_b = (const float*)d_in[6];
    const float* fc2_w = (const float*)d_in[7];
    const float* fc2_b = (const float*)d_in[8];
    const float* ln1_w = (const float*)d_in[9];
    const float* ln1_b = (const float*)d_in[10];
    const float* ln2_w = (const float*)d_in[11];
    const float* ln2_b = (const float*)d_in[12];
    const void*  pad   = d_in[13];
    float* out = (float*)d_out;

    float* p_y1;
    __half *p_q, *p_x, *p_a, *p_y1h, *p_f, *p_wi, *p_wo, *p_w1, *p_w2;
    cudaGetSymbolAddress((void**)&p_y1,  g_y1);
    cudaGetSymbolAddress((void**)&p_q,   g_q);
    cudaGetSymbolAddress((void**)&p_x,   g_x);
    cudaGetSymbolAddress((void**)&p_a,   g_a);
    cudaGetSymbolAddress((void**)&p_y1h, g_y1h);
    cudaGetSymbolAddress((void**)&p_f,   g_f);
    cudaGetSymbolAddress((void**)&p_wi,  g_wi);
    cudaGetSymbolAddress((void**)&p_wo,  g_wo);
    cudaGetSymbolAddress((void**)&p_w1,  g_w1);
    cudaGetSymbolAddress((void**)&p_w2,  g_w2);

    cudaFuncSetAttribute(gemm_f16<0,0,1>, cudaFuncAttributeMaxDynamicSharedMemorySize, SMEMG);
    cudaFuncSetAttribute(gemm_f16<0,1,0>, cudaFuncAttributeMaxDynamicSharedMemorySize, SMEMG);
    cudaFuncSetAttribute(gemm_f16<1,0,1>, cudaFuncAttributeMaxDynamicSharedMemorySize, SMEMG);
    cudaFuncSetAttribute(attn_mma, cudaFuncAttributeMaxDynamicSharedMemorySize, ATT_SMEM);

    // launches 0-4: converts (so launch index 5 = QKV GEMM gets ncu-profiled)
    convert_h<<<(MM * EE / 4 + 255) / 256, 256>>>(x, p_x, MM * EE / 4);
    convert_h<<<(3 * EE * EE / 4 + 255) / 256, 256>>>(in_w,  p_wi, 3 * EE * EE / 4);
    convert_h<<<(EE * EE / 4 + 255) / 256, 256>>>(out_w, p_wo, EE * EE / 4);
    convert_h<<<(FFD * EE / 4 + 255) / 256, 256>>>(fc1_w, p_w1, FFD * EE / 4);
    convert_h<<<(EE * FFD / 4 + 255) / 256, 256>>>(fc2_w, p_w2, EE * FFD / 4);

    // 1. QKV projection -> fp16   (launch index 5: ncu target)
    gemm_f16<0,0,1><<<dim3(3 * EE / 128, MM / 128), 128, SMEMG>>>(
        p_x, p_wi, in_b, nullptr, nullptr, p_q, MM, 3 * EE, EE);

    // mask probe (needed only before attention)
    probe_mask<<<1, 256>>>((const unsigned char*)pad);

    // 2. fp16 flash attention -> fp16
    attn_mma<<<dim3(TT / 64, HH, BB), 128, ATT_SMEM>>>(p_q, pad, p_a);

    // 3. out projection + bias + residual(x) -> fp32 y1
    gemm_f16<0,1,0><<<dim3(EE / 128, MM / 128), 128, SMEMG>>>(
        p_a, p_wo, out_b, x, p_y1, nullptr, MM, EE, EE);

    // 4. LN1 in-place + fp16 emit
    ln_kernel<1><<<MM, 256>>>(p_y1, ln1_w, ln1_b, p_y1h);

    // 5. FC1 + ReLU -> fp16
    gemm_f16<1,0,1><<<dim3(FFD / 128, MM / 128), 128, SMEMG>>>(
        p_y1h, p_w1, fc1_b, nullptr, nullptr, p_f, MM, FFD, EE);

    // 6. FC2 + bias + residual(y1) -> d_out fp32
    gemm_f16<0,1,0><<<dim3(EE / 128, MM / 128), 128, SMEMG>>>(
        p_f, p_w2, fc2_b, p_y1, out, nullptr, MM, EE, FFD);

    // 7. LN2 in-place on d_out
    ln_kernel<0><<<MM, 256>>>(out, ln2_w, ln2_b, nullptr);
}